// round 14
// baseline (speedup 1.0000x reference)
#include <cuda_runtime.h>
#include <cuda_fp16.h>
#include <math.h>
#include <stdint.h>

#define S_LEN 4096
#define HIDDEN 2048
#define HQ 16
#define HKV 4
#define DHD 128
#define QSTR (HQ*DHD)    // 2048
#define KSTR (HKV*DHD)   // 512
#define RMS_EPS 1e-6f
#define SM_SCALE 0.08838834764831845f  // 128^-0.5

// ------------------------- scratch (static device globals) ----------------------
__device__ float g_q[S_LEN * QSTR];
__device__ float g_k[S_LEN * KSTR];
__device__ float g_v[S_LEN * KSTR];

__device__ __half g_hs[S_LEN * HIDDEN];
__device__ __half g_at[S_LEN * QSTR];
__device__ __half g_qh[S_LEN * QSTR];
__device__ __half g_kh[S_LEN * KSTR];
__device__ __half g_vth[KSTR * S_LEN];   // [hk*128+d][s]
__device__ __half g_wq[QSTR * HIDDEN];
__device__ __half g_wk[KSTR * HIDDEN];
__device__ __half g_wv[KSTR * HIDDEN];
__device__ __half g_wo[HIDDEN * QSTR];

// ------------------------- helpers ----------------------------------------------
__device__ __forceinline__ uint32_t smem_u32(const void* p) {
    uint32_t a;
    asm("{ .reg .u64 t; cvta.to.shared.u64 t, %1; cvt.u32.u64 %0, t; }" : "=r"(a) : "l"(p));
    return a;
}
__device__ __forceinline__ void ldsm_x4(uint32_t* r, uint32_t addr) {
    asm volatile("ldmatrix.sync.aligned.m8n8.x4.shared.b16 {%0,%1,%2,%3}, [%4];"
                 : "=r"(r[0]), "=r"(r[1]), "=r"(r[2]), "=r"(r[3]) : "r"(addr));
}
__device__ __forceinline__ void mma_f16(float* d, const uint32_t* a, const uint32_t* b,
                                        const float* c) {
    asm volatile(
        "mma.sync.aligned.m16n8k16.row.col.f32.f16.f16.f32 "
        "{%0,%1,%2,%3}, {%4,%5,%6,%7}, {%8,%9}, {%10,%11,%12,%13};"
        : "=f"(d[0]), "=f"(d[1]), "=f"(d[2]), "=f"(d[3])
        : "r"(a[0]), "r"(a[1]), "r"(a[2]), "r"(a[3]),
          "r"(b[0]), "r"(b[1]),
          "f"(c[0]), "f"(c[1]), "f"(c[2]), "f"(c[3]));
}
__device__ __forceinline__ void cp_async16(uint32_t dst, const void* src) {
    asm volatile("cp.async.cg.shared.global [%0], [%1], 16;" :: "r"(dst), "l"(src) : "memory");
}
__device__ __forceinline__ void cp_commit() {
    asm volatile("cp.async.commit_group;" ::: "memory");
}
template<int N> __device__ __forceinline__ void cp_wait() {
    asm volatile("cp.async.wait_group %0;" :: "n"(N) : "memory");
}
// logical tile rows of 64B (32 fp16) with XOR swizzle
__device__ __forceinline__ uint32_t swz(uint32_t tileBase, int r, int c) {
    uint32_t off = r * 64 + c * 16;
    off ^= ((off >> 7) & 7) << 4;
    return tileBase + off;
}

// ------------------------- transpose device core (fp16 single) -------------------
__device__ __forceinline__ void wt_tile_h(
    const float* __restrict__ W, __half* __restrict__ Th,
    int K, int N, int n0, int k0)
{
    __shared__ float t[32][33];
    int tx = threadIdx.x & 31, ty = threadIdx.x >> 5;
#pragma unroll
    for (int j = 0; j < 4; j++)
        t[ty + 8 * j][tx] = W[(size_t)(k0 + ty + 8 * j) * N + n0 + tx];
    __syncthreads();
#pragma unroll
    for (int j = 0; j < 4; j++) {
        size_t o = (size_t)(n0 + ty + 8 * j) * K + k0 + tx;
        Th[o] = __float2half(t[tx][ty + 8 * j]);
    }
}

// merged input prep: hs fp16 convert (8192 blocks) + 4 weight transposes (10240)
__global__ __launch_bounds__(256) void prep_inputs(
    const float* __restrict__ hs,
    const float* __restrict__ wq, const float* __restrict__ wk,
    const float* __restrict__ wv, const float* __restrict__ wo,
    __half* __restrict__ hsh,
    __half* __restrict__ wqt, __half* __restrict__ wkt,
    __half* __restrict__ wvt, __half* __restrict__ wot)
{
    int b = blockIdx.x;
    if (b < 8192) {
        int i = (b * 256 + threadIdx.x) * 4;
        float4 v = *(const float4*)(hs + i);
        *(__half2*)(hsh + i)     = __floats2half2_rn(v.x, v.y);
        *(__half2*)(hsh + i + 2) = __floats2half2_rn(v.z, v.w);
        return;
    }
    b -= 8192;
    if (b < 4096)
        wt_tile_h(wq, wqt, HIDDEN, QSTR, (b & 63) * 32, (b >> 6) * 32);
    else if (b < 5120) {
        int l = b - 4096;
        wt_tile_h(wk, wkt, HIDDEN, KSTR, (l & 15) * 32, (l >> 4) * 32);
    } else if (b < 6144) {
        int l = b - 5120;
        wt_tile_h(wv, wvt, HIDDEN, KSTR, (l & 15) * 32, (l >> 4) * 32);
    } else {
        int l = b - 6144;
        wt_tile_h(wo, wot, QSTR, HIDDEN, (l & 63) * 32, (l >> 6) * 32);
    }
}

// ------------------------- single-fp16 HMMA GEMM core (128x128, 512 thr) ---------
// C = A[M,K] @ B[N,K]^T. CTA 128x128, 16 warps (4x4), warp tile 32x32,
// K-chunk 64, double-buffered 64 KB smem. L2 traffic factor 4/256 (was 6/256).
#define GSUB   8192                     // 128x32 fp16 subtile
#define GSTAGE (4 * GSUB)               // A0,A1,B0,B1 = 32768
#define G_SMEM (2 * GSTAGE)             // 65536

__device__ __forceinline__ void gemm_stage(
    uint32_t st, int k0, int tid, int K,
    const __half* __restrict__ A0, const __half* __restrict__ B0)
{
#pragma unroll
    for (int s2 = 0; s2 < 4; s2++) {
        int i = tid + 512 * s2;
        const __half* base = (i < 1024) ? A0 : B0;
        int j = i & 1023;
        int sub = j >> 9, r = (j >> 2) & 127, x = j & 3;
        uint32_t dst = st + (i < 1024 ? 0 : 2 * GSUB) + sub * GSUB;
        cp_async16(swz(dst, r, x),
                   base + (size_t)r * K + k0 + sub * 32 + x * 8);
    }
    cp_commit();
}

__device__ __forceinline__ void gemm_core(
    const __half* __restrict__ A0, const __half* __restrict__ B0,
    float* __restrict__ C0, int ldc, int K, uint32_t sb)
{
    const int tid  = threadIdx.x;
    const int wid  = tid >> 5;
    const int lane = tid & 31;
    const int mBase = (wid >> 2) * 32;
    const int nBase = (wid & 3) * 32;
    const int lr = lane & 15, lc = lane >> 4;

    float acc[2][4][4];
#pragma unroll
    for (int f = 0; f < 2; f++)
#pragma unroll
        for (int j = 0; j < 4; j++)
#pragma unroll
            for (int x = 0; x < 4; x++) acc[f][j][x] = 0.f;

    const int nChunks = K >> 6;
    gemm_stage(sb, 0, tid, K, A0, B0);

    for (int kc = 0; kc < nChunks; kc++) {
        const uint32_t st = sb + (kc & 1) * GSTAGE;
        if (kc + 1 < nChunks) {
            gemm_stage(sb + ((kc + 1) & 1) * GSTAGE, (kc + 1) << 6, tid, K, A0, B0);
            cp_wait<1>();
        } else {
            cp_wait<0>();
        }
        __syncthreads();

#pragma unroll
        for (int s16 = 0; s16 < 4; s16++) {
            const int sub = s16 >> 1;
            const int ch  = (s16 & 1) * 2 + lc;
            const uint32_t tA = st + sub * GSUB;
            const uint32_t tB = st + 2 * GSUB + sub * GSUB;

            uint32_t ah[2][4], bb[2][4];
#pragma unroll
            for (int f = 0; f < 2; f++)
                ldsm_x4(ah[f], swz(tA, mBase + f * 16 + lr, ch));
#pragma unroll
            for (int g = 0; g < 2; g++)
                ldsm_x4(bb[g], swz(tB, nBase + g * 16 + lr, ch));
#pragma unroll
            for (int f = 0; f < 2; f++)
#pragma unroll
                for (int j = 0; j < 4; j++) {
                    uint32_t bfr[2] = {bb[j >> 1][j & 1], bb[j >> 1][2 + (j & 1)]};
                    mma_f16(acc[f][j], ah[f], bfr, acc[f][j]);
                }
        }
        __syncthreads();
    }

    const int erow = lane >> 2;
    const int ecol = (lane & 3) * 2;
#pragma unroll
    for (int f = 0; f < 2; f++) {
        int rl = mBase + f * 16 + erow;
#pragma unroll
        for (int j = 0; j < 4; j++) {
            int cl = nBase + j * 8 + ecol;
            *(float2*)(C0 + (size_t)rl * ldc + cl)       = make_float2(acc[f][j][0], acc[f][j][1]);
            *(float2*)(C0 + (size_t)(rl + 8) * ldc + cl) = make_float2(acc[f][j][2], acc[f][j][3]);
        }
    }
}

// fused QKV projection: grid.x = 24 (16 q, 4 k, 4 v tiles of width 128)
__global__ __launch_bounds__(512, 1) void gemm_qkv(
    const __half* __restrict__ A,
    const __half* __restrict__ wqt, const __half* __restrict__ wkt,
    const __half* __restrict__ wvt,
    float* __restrict__ Q, float* __restrict__ K, float* __restrict__ V)
{
    extern __shared__ char smc[];
    const uint32_t sb = smem_u32(smc);
    const int bx = blockIdx.x;
    const int m0 = blockIdx.y * 128;

    const __half* B;
    float* C;
    int n0, ldc;
    if (bx < 16)      { B = wqt; C = Q; n0 = bx * 128;        ldc = QSTR; }
    else if (bx < 20) { B = wkt; C = K; n0 = (bx - 16) * 128; ldc = KSTR; }
    else              { B = wvt; C = V; n0 = (bx - 20) * 128; ldc = KSTR; }

    gemm_core(A + (size_t)m0 * HIDDEN, B + (size_t)n0 * HIDDEN,
              C + (size_t)m0 * ldc + n0, ldc, HIDDEN, sb);
}

__global__ __launch_bounds__(512, 1) void gemm_f16(
    const __half* __restrict__ A, const __half* __restrict__ B,
    float* __restrict__ C, int M, int N, int K)
{
    extern __shared__ char smc[];
    const uint32_t sb = smem_u32(smc);
    const int m0 = blockIdx.y * 128, n0 = blockIdx.x * 128;
    gemm_core(A + (size_t)m0 * K, B + (size_t)n0 * K,
              C + (size_t)m0 * N + n0, N, K, sb);
}

// ------------------------- fused attention prep (one launch) ---------------------
__device__ __forceinline__ void rms_rope_rows_h(
    const float* __restrict__ in, const float* __restrict__ cosp,
    const float* __restrict__ sinp, const float* __restrict__ w,
    int nh, float outScale, int rowBase, __half* __restrict__ H)
{
    const int lane = threadIdx.x & 31;
    const int rowIdx = rowBase + (threadIdx.x >> 5);
    const int s = rowIdx / nh;
    const int d0 = lane * 2;

    const float* x = in + (size_t)rowIdx * DHD;
    float2 a = *(const float2*)(x + d0);
    float2 b = *(const float2*)(x + 64 + d0);

    float ss = a.x * a.x + a.y * a.y + b.x * b.x + b.y * b.y;
#pragma unroll
    for (int o = 16; o > 0; o >>= 1) ss += __shfl_xor_sync(0xFFFFFFFFu, ss, o);
    float inv = rsqrtf(ss * (1.0f / DHD) + RMS_EPS);

    float2 wa = *(const float2*)(w + d0);
    float2 wb = *(const float2*)(w + 64 + d0);
    const float* cs = cosp + (size_t)s * DHD;
    const float* sn = sinp + (size_t)s * DHD;
    float2 ca = *(const float2*)(cs + d0), cb = *(const float2*)(cs + 64 + d0);
    float2 sa = *(const float2*)(sn + d0), sb2 = *(const float2*)(sn + 64 + d0);

    float xa0 = a.x * inv * wa.x, xa1 = a.y * inv * wa.y;
    float xb0 = b.x * inv * wb.x, xb1 = b.y * inv * wb.y;
    float oa0 = (xa0 * ca.x - xb0 * sa.x) * outScale;
    float oa1 = (xa1 * ca.y - xb1 * sa.y) * outScale;
    float ob0 = (xb0 * cb.x + xa0 * sb2.x) * outScale;
    float ob1 = (xb1 * cb.y + xa1 * sb2.y) * outScale;

    size_t off = (size_t)rowIdx * DHD + d0;
    *(__half2*)(H + off)      = __floats2half2_rn(oa0, oa1);
    *(__half2*)(H + off + 64) = __floats2half2_rn(ob0, ob1);
}

__global__ __launch_bounds__(256) void prep_attn(
    const float* __restrict__ qp, const float* __restrict__ kp,
    const float* __restrict__ vp,
    const float* __restrict__ cosp, const float* __restrict__ sinp,
    const float* __restrict__ qnw, const float* __restrict__ knw,
    __half* __restrict__ qh, __half* __restrict__ kh,
    __half* __restrict__ vth)
{
    int b = blockIdx.x;
    if (b < 8192)
        rms_rope_rows_h(qp, cosp, sinp, qnw, HQ, SM_SCALE, b * 8, qh);
    else if (b < 10240)
        rms_rope_rows_h(kp, cosp, sinp, knw, HKV, 1.0f, (b - 8192) * 8, kh);
    else {
        int l = b - 10240;
        wt_tile_h(vp, vth, S_LEN, KSTR, (l & 15) * 32, (l >> 4) * 32);
    }
}

// ------------------------- fp16 HMMA causal flash attention ----------------------
#define FBM 64
#define FBN 64
#define FQ_OFF 0
#define FK_OFF(i) (16384 + (i) * 16384)
#define FV_OFF(i) (49152 + (i) * 16384)
#define F_SMEM 81920

__device__ __forceinline__ void flash_load_k(
    uint32_t dst, int tid, int kg0, int hk, const __half* Kh)
{
#pragma unroll
    for (int s = 0; s < 8; s++) {
        int i = tid + 128 * s;
        int c = i >> 8, r = (i >> 2) & 63, x = i & 3;
        cp_async16(swz(dst + c * 4096, r, x),
                   Kh + ((size_t)(kg0 + r) * HKV + hk) * DHD + c * 32 + x * 8);
    }
}
__device__ __forceinline__ void flash_load_v(
    uint32_t dst, int tid, int kg0, int hk, const __half* Vth)
{
#pragma unroll
    for (int s = 0; s < 8; s++) {
        int i = tid + 128 * s;
        int kc = i >> 9, r = (i >> 2) & 127, x = i & 3;
        cp_async16(swz(dst + kc * 8192, r, x),
                   Vth + (size_t)(hk * DHD + r) * S_LEN + kg0 + kc * 32 + x * 8);
    }
}

__global__ __launch_bounds__(128, 2) void flash_hmma(
    const __half* __restrict__ Qh, const __half* __restrict__ Kh,
    const __half* __restrict__ Vth,
    __half* __restrict__ O)
{
    extern __shared__ char smf[];
    const uint32_t sb = smem_u32(smf);
    const int tid = threadIdx.x, wid = tid >> 5, lane = tid & 31;
    const int qt = (int)gridDim.x - 1 - (int)blockIdx.x;   // heavy tiles first
    const int h = blockIdx.y, hk = h >> 2;
    const int qm0 = qt * FBM;
    const int wBase = wid * 16;
    const int lr = lane & 15, lc = lane >> 4;
    const int erow = lane >> 2, q4 = lane & 3;

#pragma unroll
    for (int s = 0; s < 8; s++) {
        int i = tid + 128 * s;
        int c = i >> 8, r = (i >> 2) & 63, x = i & 3;
        cp_async16(swz(sb + FQ_OFF + c * 4096, r, x),
                   Qh + ((size_t)(qm0 + r) * HQ + h) * DHD + c * 32 + x * 8);
    }
    flash_load_k(sb + FK_OFF(0), tid, 0, hk, Kh);
    cp_commit();
    flash_load_v(sb + FV_OFF(0), tid, 0, hk, Vth);
    cp_commit();

    uint32_t qf[8][4];
    float oacc[16][4];
#pragma unroll
    for (int jj = 0; jj < 16; jj++)
#pragma unroll
        for (int x = 0; x < 4; x++) oacc[jj][x] = 0.f;
    float m0 = -1e30f, m1 = -1e30f, l0 = 0.f, l1 = 0.f;

    for (int t = 0; t <= qt; t++) {
        const uint32_t kb = sb + FK_OFF(t & 1);
        const uint32_t vb = sb + FV_OFF(t & 1);

        cp_wait<1>();
        __syncthreads();

        if (t == 0) {
#pragma unroll
            for (int kk = 0; kk < 8; kk++) {
                int c = kk >> 1, x = (kk & 1) * 2 + lc;
                ldsm_x4(qf[kk], swz(sb + FQ_OFF + c * 4096, wBase + lr, x));
            }
        }

        if (t < qt) {
            flash_load_k(sb + FK_OFF((t + 1) & 1), tid, (t + 1) * FBN, hk, Kh);
            cp_commit();
        }

        float sacc[8][4];
#pragma unroll
        for (int j = 0; j < 8; j++)
#pragma unroll
            for (int x = 0; x < 4; x++) sacc[j][x] = 0.f;

#pragma unroll
        for (int kk = 0; kk < 8; kk++) {
            int c = kk >> 1, x = (kk & 1) * 2 + lc;
            uint32_t kbf[4][4];
#pragma unroll
            for (int g = 0; g < 4; g++)
                ldsm_x4(kbf[g], swz(kb + c * 4096, g * 16 + lr, x));
#pragma unroll
            for (int j = 0; j < 8; j++) {
                uint32_t bf[2] = {kbf[j >> 1][j & 1], kbf[j >> 1][(j & 1) + 2]};
                mma_f16(sacc[j], qf[kk], bf, sacc[j]);
            }
        }

        if (t == qt) {
            int row0 = qm0 + wBase + erow, row1 = row0 + 8;
            int colb = t * FBN + q4 * 2;
#pragma unroll
            for (int j = 0; j < 8; j++) {
                int c0 = colb + j * 8, c1 = c0 + 1;
                if (c0 > row0) sacc[j][0] = -1e30f;
                if (c1 > row0) sacc[j][1] = -1e30f;
                if (c0 > row1) sacc[j][2] = -1e30f;
                if (c1 > row1) sacc[j][3] = -1e30f;
            }
        }

        float mx0 = -1e30f, mx1 = -1e30f;
#pragma unroll
        for (int j = 0; j < 8; j++) {
            mx0 = fmaxf(mx0, fmaxf(sacc[j][0], sacc[j][1]));
            mx1 = fmaxf(mx1, fmaxf(sacc[j][2], sacc[j][3]));
        }
        mx0 = fmaxf(mx0, __shfl_xor_sync(0xFFFFFFFFu, mx0, 1));
        mx0 = fmaxf(mx0, __shfl_xor_sync(0xFFFFFFFFu, mx0, 2));
        mx1 = fmaxf(mx1, __shfl_xor_sync(0xFFFFFFFFu, mx1, 1));
        mx1 = fmaxf(mx1, __shfl_xor_sync(0xFFFFFFFFu, mx1, 2));
        float mn0 = fmaxf(m0, mx0), mn1 = fmaxf(m1, mx1);
        float a0 = __expf(m0 - mn0), a1 = __expf(m1 - mn1);
        float s0 = 0.f, s1 = 0.f;
#pragma unroll
        for (int j = 0; j < 8; j++) {
            float p0 = __expf(sacc[j][0] - mn0); sacc[j][0] = p0; s0 += p0;
            float p1 = __expf(sacc[j][1] - mn0); sacc[j][1] = p1; s0 += p1;
            float p2 = __expf(sacc[j][2] - mn1); sacc[j][2] = p2; s1 += p2;
            float p3 = __expf(sacc[j][3] - mn1); sacc[j][3] = p3; s1 += p3;
        }
        s0 += __shfl_xor_sync(0xFFFFFFFFu, s0, 1);
        s0 += __shfl_xor_sync(0xFFFFFFFFu, s0, 2);
        s1 += __shfl_xor_sync(0xFFFFFFFFu, s1, 1);
        s1 += __shfl_xor_sync(0xFFFFFFFFu, s1, 2);
        l0 = l0 * a0 + s0;
        l1 = l1 * a1 + s1;
        m0 = mn0; m1 = mn1;
#pragma unroll
        for (int jj = 0; jj < 16; jj++) {
            oacc[jj][0] *= a0; oacc[jj][1] *= a0;
            oacc[jj][2] *= a1; oacc[jj][3] *= a1;
        }

        if (t < qt) cp_wait<1>(); else cp_wait<0>();
        __syncthreads();

        if (t < qt) {
            flash_load_v(sb + FV_OFF((t + 1) & 1), tid, (t + 1) * FBN, hk, Vth);
            cp_commit();
        }

        // O += P @ V  (single fp16 P)
#pragma unroll
        for (int tt = 0; tt < 4; tt++) {
            uint32_t ph[4];
            {
                __half2 v0 = __floats2half2_rn(sacc[2*tt][0],   sacc[2*tt][1]);
                __half2 v1 = __floats2half2_rn(sacc[2*tt][2],   sacc[2*tt][3]);
                __half2 v2 = __floats2half2_rn(sacc[2*tt+1][0], sacc[2*tt+1][1]);
                __half2 v3 = __floats2half2_rn(sacc[2*tt+1][2], sacc[2*tt+1][3]);
                ph[0] = *(uint32_t*)&v0; ph[1] = *(uint32_t*)&v1;
                ph[2] = *(uint32_t*)&v2; ph[3] = *(uint32_t*)&v3;
            }
            int kc = tt >> 1, x = (tt & 1) * 2 + lc;
            uint32_t vbf[8][4];
#pragma unroll
            for (int g = 0; g < 8; g++)
                ldsm_x4(vbf[g], swz(vb + kc * 8192, g * 16 + lr, x));
#pragma unroll
            for (int jj = 0; jj < 16; jj++) {
                uint32_t bf[2] = {vbf[jj >> 1][jj & 1], vbf[jj >> 1][(jj & 1) + 2]};
                mma_f16(oacc[jj], ph, bf, oacc[jj]);
            }
        }
    }

    // epilogue: divide by l, write single fp16
    float il0 = 1.0f / l0, il1 = 1.0f / l1;
    int row0 = qm0 + wBase + erow;
#pragma unroll
    for (int jj = 0; jj < 16; jj++) {
        int col = jj * 8 + q4 * 2;
        *(__half2*)(O + (size_t)row0 * QSTR + h * DHD + col) =
            __floats2half2_rn(oacc[jj][0] * il0, oacc[jj][1] * il0);
        *(__half2*)(O + (size_t)(row0 + 8) * QSTR + h * DHD + col) =
            __floats2half2_rn(oacc[jj][2] * il1, oacc[jj][3] * il1);
    }
}

// ------------------------- launch -----------------------------------------------
extern "C" void kernel_launch(void* const* d_in, const int* in_sizes, int n_in,
                              void* d_out, int out_size)
{
    (void)in_sizes; (void)n_in; (void)out_size;
    const float* hs   = (const float*)d_in[0];
    const float* cosp = (const float*)d_in[1];
    const float* sinp = (const float*)d_in[2];
    const float* wq   = (const float*)d_in[3];
    const float* wk   = (const float*)d_in[4];
    const float* wv   = (const float*)d_in[5];
    const float* wo   = (const float*)d_in[6];
    const float* qnw  = (const float*)d_in[7];
    const float* knw  = (const float*)d_in[8];
    float* out = (float*)d_out;

    float *qp, *kp, *vp;
    cudaGetSymbolAddress((void**)&qp, g_q);
    cudaGetSymbolAddress((void**)&kp, g_k);
    cudaGetSymbolAddress((void**)&vp, g_v);
    __half *hsh, *ath, *qh, *kh, *vth;
    __half *wqt, *wkt, *wvt, *wot;
    cudaGetSymbolAddress((void**)&hsh, g_hs);
    cudaGetSymbolAddress((void**)&ath, g_at);
    cudaGetSymbolAddress((void**)&qh, g_qh);
    cudaGetSymbolAddress((void**)&kh, g_kh);
    cudaGetSymbolAddress((void**)&vth, g_vth);
    cudaGetSymbolAddress((void**)&wqt, g_wq);
    cudaGetSymbolAddress((void**)&wkt, g_wk);
    cudaGetSymbolAddress((void**)&wvt, g_wv);
    cudaGetSymbolAddress((void**)&wot, g_wo);

    cudaFuncSetAttribute(gemm_qkv, cudaFuncAttributeMaxDynamicSharedMemorySize, G_SMEM);
    cudaFuncSetAttribute(gemm_f16, cudaFuncAttributeMaxDynamicSharedMemorySize, G_SMEM);
    cudaFuncSetAttribute(flash_hmma, cudaFuncAttributeMaxDynamicSharedMemorySize, F_SMEM);

    // 1) input prep: hs -> fp16, weight transposes (one launch)
    prep_inputs<<<18432, 256>>>(hs, wq, wk, wv, wo, hsh,
                                wqt, wkt, wvt, wot);
    // 2) fused QKV projection (fp16, 128x128 tiles)
    gemm_qkv<<<dim3(24, S_LEN / 128), 512, G_SMEM>>>(
        hsh, wqt, wkt, wvt, qp, kp, vp);
    // 3) attention prep: rms+rope Q/K -> fp16, V -> transposed fp16
    prep_attn<<<12288, 256>>>(qp, kp, vp, cosp, sinp, qnw, knw, qh, kh, vth);
    // 4) causal flash attention (fp16)
    flash_hmma<<<dim3(S_LEN / FBM, HQ), 128, F_SMEM>>>(qh, kh, vth, ath);
    // 5) output projection (fp16, 128x128 tiles)
    gemm_f16<<<dim3(HIDDEN / 128, S_LEN / 128), 512, G_SMEM>>>(
        ath, wot, out, S_LEN, HIDDEN, QSTR);
}

// round 15
// speedup vs baseline: 1.0889x; 1.0889x over previous
#include <cuda_runtime.h>
#include <cuda_fp16.h>
#include <math.h>
#include <stdint.h>

#define S_LEN 4096
#define HIDDEN 2048
#define HQ 16
#define HKV 4
#define DHD 128
#define QSTR (HQ*DHD)    // 2048
#define KSTR (HKV*DHD)   // 512
#define RMS_EPS 1e-6f
#define SM_SCALE 0.08838834764831845f       // 128^-0.5
#define LOG2E 1.4426950408889634f
#define SM_SCALE_L2 (SM_SCALE * LOG2E)      // folded: scores in log2 domain

// ------------------------- scratch (static device globals) ----------------------
__device__ float g_q[S_LEN * QSTR];
__device__ float g_k[S_LEN * KSTR];
__device__ float g_v[S_LEN * KSTR];

__device__ __half g_hs[S_LEN * HIDDEN];
__device__ __half g_at[S_LEN * QSTR];
__device__ __half g_qh[S_LEN * QSTR];
__device__ __half g_kh[S_LEN * KSTR];
__device__ __half g_vth[KSTR * S_LEN];   // [hk*128+d][s]
__device__ __half g_wq[QSTR * HIDDEN];
__device__ __half g_wk[KSTR * HIDDEN];
__device__ __half g_wv[KSTR * HIDDEN];
__device__ __half g_wo[HIDDEN * QSTR];

// ------------------------- helpers ----------------------------------------------
__device__ __forceinline__ uint32_t smem_u32(const void* p) {
    uint32_t a;
    asm("{ .reg .u64 t; cvta.to.shared.u64 t, %1; cvt.u32.u64 %0, t; }" : "=r"(a) : "l"(p));
    return a;
}
__device__ __forceinline__ void ldsm_x4(uint32_t* r, uint32_t addr) {
    asm volatile("ldmatrix.sync.aligned.m8n8.x4.shared.b16 {%0,%1,%2,%3}, [%4];"
                 : "=r"(r[0]), "=r"(r[1]), "=r"(r[2]), "=r"(r[3]) : "r"(addr));
}
__device__ __forceinline__ void mma_f16(float* d, const uint32_t* a, const uint32_t* b,
                                        const float* c) {
    asm volatile(
        "mma.sync.aligned.m16n8k16.row.col.f32.f16.f16.f32 "
        "{%0,%1,%2,%3}, {%4,%5,%6,%7}, {%8,%9}, {%10,%11,%12,%13};"
        : "=f"(d[0]), "=f"(d[1]), "=f"(d[2]), "=f"(d[3])
        : "r"(a[0]), "r"(a[1]), "r"(a[2]), "r"(a[3]),
          "r"(b[0]), "r"(b[1]),
          "f"(c[0]), "f"(c[1]), "f"(c[2]), "f"(c[3]));
}
__device__ __forceinline__ void cp_async16(uint32_t dst, const void* src) {
    asm volatile("cp.async.cg.shared.global [%0], [%1], 16;" :: "r"(dst), "l"(src) : "memory");
}
__device__ __forceinline__ void cp_commit() {
    asm volatile("cp.async.commit_group;" ::: "memory");
}
template<int N> __device__ __forceinline__ void cp_wait() {
    asm volatile("cp.async.wait_group %0;" :: "n"(N) : "memory");
}
// logical tile rows of 64B (32 fp16) with XOR swizzle
__device__ __forceinline__ uint32_t swz(uint32_t tileBase, int r, int c) {
    uint32_t off = r * 64 + c * 16;
    off ^= ((off >> 7) & 7) << 4;
    return tileBase + off;
}

// ------------------------- transpose device core (fp16 single) -------------------
__device__ __forceinline__ void wt_tile_h(
    const float* __restrict__ W, __half* __restrict__ Th,
    int K, int N, int n0, int k0)
{
    __shared__ float t[32][33];
    int tx = threadIdx.x & 31, ty = threadIdx.x >> 5;
#pragma unroll
    for (int j = 0; j < 4; j++)
        t[ty + 8 * j][tx] = W[(size_t)(k0 + ty + 8 * j) * N + n0 + tx];
    __syncthreads();
#pragma unroll
    for (int j = 0; j < 4; j++) {
        size_t o = (size_t)(n0 + ty + 8 * j) * K + k0 + tx;
        Th[o] = __float2half(t[tx][ty + 8 * j]);
    }
}

// merged input prep: hs fp16 convert (8192 blocks) + 4 weight transposes (10240)
__global__ __launch_bounds__(256) void prep_inputs(
    const float* __restrict__ hs,
    const float* __restrict__ wq, const float* __restrict__ wk,
    const float* __restrict__ wv, const float* __restrict__ wo,
    __half* __restrict__ hsh,
    __half* __restrict__ wqt, __half* __restrict__ wkt,
    __half* __restrict__ wvt, __half* __restrict__ wot)
{
    int b = blockIdx.x;
    if (b < 8192) {
        int i = (b * 256 + threadIdx.x) * 4;
        float4 v = *(const float4*)(hs + i);
        *(__half2*)(hsh + i)     = __floats2half2_rn(v.x, v.y);
        *(__half2*)(hsh + i + 2) = __floats2half2_rn(v.z, v.w);
        return;
    }
    b -= 8192;
    if (b < 4096)
        wt_tile_h(wq, wqt, HIDDEN, QSTR, (b & 63) * 32, (b >> 6) * 32);
    else if (b < 5120) {
        int l = b - 4096;
        wt_tile_h(wk, wkt, HIDDEN, KSTR, (l & 15) * 32, (l >> 4) * 32);
    } else if (b < 6144) {
        int l = b - 5120;
        wt_tile_h(wv, wvt, HIDDEN, KSTR, (l & 15) * 32, (l >> 4) * 32);
    } else {
        int l = b - 6144;
        wt_tile_h(wo, wot, QSTR, HIDDEN, (l & 63) * 32, (l >> 6) * 32);
    }
}

// ------------------------- single-fp16 HMMA GEMM core (K-chunk 64) ---------------
// C = A[M,K] @ B[N,K]^T. CTA 128x64, warp tile 32x32, 8 warps, 2 CTAs/SM.
#define GA_SUB 8192                    // 128x32 fp16 subtile
#define GB_SUB 4096                    // 64x32 fp16 subtile
#define GSTAGE (2 * GA_SUB + 2 * GB_SUB)   // 24576
#define G_SMEM (2 * GSTAGE)                // 49152

__device__ __forceinline__ void gemm_stage(
    uint32_t st, int k0, int tid, int K,
    const __half* __restrict__ A0, const __half* __restrict__ B0)
{
#pragma unroll
    for (int s2 = 0; s2 < 6; s2++) {
        int i = tid + 256 * s2;
        if (i < 1024) {
            int idx = i >> 9;
            int r = (i >> 2) & 127, x = i & 3;
            cp_async16(swz(st + idx * GA_SUB, r, x),
                       A0 + (size_t)r * K + k0 + idx * 32 + x * 8);
        } else {
            int j = i - 1024;
            int idx = j >> 8;
            int r = (j >> 2) & 63, x = j & 3;
            cp_async16(swz(st + 2 * GA_SUB + idx * GB_SUB, r, x),
                       B0 + (size_t)r * K + k0 + idx * 32 + x * 8);
        }
    }
    cp_commit();
}

__device__ __forceinline__ void gemm_core(
    const __half* __restrict__ A0, const __half* __restrict__ B0,
    float* __restrict__ C0, int ldc, int K, uint32_t sb)
{
    const int tid  = threadIdx.x;
    const int wid  = tid >> 5;
    const int lane = tid & 31;
    const int mBase = (wid >> 1) * 32;
    const int nBase = (wid & 1) * 32;
    const int lr = lane & 15, lc = lane >> 4;

    float acc[2][4][4];
#pragma unroll
    for (int f = 0; f < 2; f++)
#pragma unroll
        for (int j = 0; j < 4; j++)
#pragma unroll
            for (int x = 0; x < 4; x++) acc[f][j][x] = 0.f;

    const int nChunks = K >> 6;
    gemm_stage(sb, 0, tid, K, A0, B0);

    for (int kc = 0; kc < nChunks; kc++) {
        const uint32_t st = sb + (kc & 1) * GSTAGE;
        if (kc + 1 < nChunks) {
            gemm_stage(sb + ((kc + 1) & 1) * GSTAGE, (kc + 1) << 6, tid, K, A0, B0);
            cp_wait<1>();
        } else {
            cp_wait<0>();
        }
        __syncthreads();

#pragma unroll
        for (int s16 = 0; s16 < 4; s16++) {
            const int sub = s16 >> 1;
            const int ch  = (s16 & 1) * 2 + lc;
            const uint32_t tA = st + sub * GA_SUB;
            const uint32_t tB = st + 2 * GA_SUB + sub * GB_SUB;

            uint32_t ah[2][4], bb[2][4];
#pragma unroll
            for (int f = 0; f < 2; f++)
                ldsm_x4(ah[f], swz(tA, mBase + f * 16 + lr, ch));
#pragma unroll
            for (int g = 0; g < 2; g++)
                ldsm_x4(bb[g], swz(tB, nBase + g * 16 + lr, ch));
#pragma unroll
            for (int f = 0; f < 2; f++)
#pragma unroll
                for (int j = 0; j < 4; j++) {
                    uint32_t bfr[2] = {bb[j >> 1][j & 1], bb[j >> 1][2 + (j & 1)]};
                    mma_f16(acc[f][j], ah[f], bfr, acc[f][j]);
                }
        }
        __syncthreads();
    }

    const int erow = lane >> 2;
    const int ecol = (lane & 3) * 2;
#pragma unroll
    for (int f = 0; f < 2; f++) {
        int rl = mBase + f * 16 + erow;
#pragma unroll
        for (int j = 0; j < 4; j++) {
            int cl = nBase + j * 8 + ecol;
            *(float2*)(C0 + (size_t)rl * ldc + cl)       = make_float2(acc[f][j][0], acc[f][j][1]);
            *(float2*)(C0 + (size_t)(rl + 8) * ldc + cl) = make_float2(acc[f][j][2], acc[f][j][3]);
        }
    }
}

__global__ __launch_bounds__(256, 2) void gemm_qkv(
    const __half* __restrict__ A,
    const __half* __restrict__ wqt, const __half* __restrict__ wkt,
    const __half* __restrict__ wvt,
    float* __restrict__ Q, float* __restrict__ K, float* __restrict__ V)
{
    extern __shared__ char smc[];
    const uint32_t sb = smem_u32(smc);
    const int bx = blockIdx.x;
    const int m0 = blockIdx.y * 128;

    const __half* B;
    float* C;
    int n0, ldc;
    if (bx < 32)      { B = wqt; C = Q; n0 = bx * 64;        ldc = QSTR; }
    else if (bx < 40) { B = wkt; C = K; n0 = (bx - 32) * 64; ldc = KSTR; }
    else              { B = wvt; C = V; n0 = (bx - 40) * 64; ldc = KSTR; }

    gemm_core(A + (size_t)m0 * HIDDEN, B + (size_t)n0 * HIDDEN,
              C + (size_t)m0 * ldc + n0, ldc, HIDDEN, sb);
}

__global__ __launch_bounds__(256, 2) void gemm_f16(
    const __half* __restrict__ A, const __half* __restrict__ B,
    float* __restrict__ C, int M, int N, int K)
{
    extern __shared__ char smc[];
    const uint32_t sb = smem_u32(smc);
    const int m0 = blockIdx.y * 128, n0 = blockIdx.x * 64;
    gemm_core(A + (size_t)m0 * K, B + (size_t)n0 * K,
              C + (size_t)m0 * N + n0, N, K, sb);
}

// ------------------------- fused attention prep (one launch) ---------------------
__device__ __forceinline__ void rms_rope_rows_h(
    const float* __restrict__ in, const float* __restrict__ cosp,
    const float* __restrict__ sinp, const float* __restrict__ w,
    int nh, float outScale, int rowBase, __half* __restrict__ H)
{
    const int lane = threadIdx.x & 31;
    const int rowIdx = rowBase + (threadIdx.x >> 5);
    const int s = rowIdx / nh;
    const int d0 = lane * 2;

    const float* x = in + (size_t)rowIdx * DHD;
    float2 a = *(const float2*)(x + d0);
    float2 b = *(const float2*)(x + 64 + d0);

    float ss = a.x * a.x + a.y * a.y + b.x * b.x + b.y * b.y;
#pragma unroll
    for (int o = 16; o > 0; o >>= 1) ss += __shfl_xor_sync(0xFFFFFFFFu, ss, o);
    float inv = rsqrtf(ss * (1.0f / DHD) + RMS_EPS);

    float2 wa = *(const float2*)(w + d0);
    float2 wb = *(const float2*)(w + 64 + d0);
    const float* cs = cosp + (size_t)s * DHD;
    const float* sn = sinp + (size_t)s * DHD;
    float2 ca = *(const float2*)(cs + d0), cb = *(const float2*)(cs + 64 + d0);
    float2 sa = *(const float2*)(sn + d0), sb2 = *(const float2*)(sn + 64 + d0);

    float xa0 = a.x * inv * wa.x, xa1 = a.y * inv * wa.y;
    float xb0 = b.x * inv * wb.x, xb1 = b.y * inv * wb.y;
    float oa0 = (xa0 * ca.x - xb0 * sa.x) * outScale;
    float oa1 = (xa1 * ca.y - xb1 * sa.y) * outScale;
    float ob0 = (xb0 * cb.x + xa0 * sb2.x) * outScale;
    float ob1 = (xb1 * cb.y + xa1 * sb2.y) * outScale;

    size_t off = (size_t)rowIdx * DHD + d0;
    *(__half2*)(H + off)      = __floats2half2_rn(oa0, oa1);
    *(__half2*)(H + off + 64) = __floats2half2_rn(ob0, ob1);
}

__global__ __launch_bounds__(256) void prep_attn(
    const float* __restrict__ qp, const float* __restrict__ kp,
    const float* __restrict__ vp,
    const float* __restrict__ cosp, const float* __restrict__ sinp,
    const float* __restrict__ qnw, const float* __restrict__ knw,
    __half* __restrict__ qh, __half* __restrict__ kh,
    __half* __restrict__ vth)
{
    int b = blockIdx.x;
    if (b < 8192)
        rms_rope_rows_h(qp, cosp, sinp, qnw, HQ, SM_SCALE_L2, b * 8, qh);
    else if (b < 10240)
        rms_rope_rows_h(kp, cosp, sinp, knw, HKV, 1.0f, (b - 8192) * 8, kh);
    else {
        int l = b - 10240;
        wt_tile_h(vp, vth, S_LEN, KSTR, (l & 15) * 32, (l >> 4) * 32);
    }
}

// ------------------------- fp16 HMMA causal flash attention ----------------------
// Scores natively in log2 domain (log2e folded into Q scale) -> exp2f softmax.
#define FBM 64
#define FBN 64
#define FQ_OFF 0
#define FK_OFF(i) (16384 + (i) * 16384)
#define FV_OFF(i) (49152 + (i) * 16384)
#define F_SMEM 81920

__device__ __forceinline__ void flash_load_k(
    uint32_t dst, int tid, int kg0, int hk, const __half* Kh)
{
#pragma unroll
    for (int s = 0; s < 8; s++) {
        int i = tid + 128 * s;
        int c = i >> 8, r = (i >> 2) & 63, x = i & 3;
        cp_async16(swz(dst + c * 4096, r, x),
                   Kh + ((size_t)(kg0 + r) * HKV + hk) * DHD + c * 32 + x * 8);
    }
}
__device__ __forceinline__ void flash_load_v(
    uint32_t dst, int tid, int kg0, int hk, const __half* Vth)
{
#pragma unroll
    for (int s = 0; s < 8; s++) {
        int i = tid + 128 * s;
        int kc = i >> 9, r = (i >> 2) & 127, x = i & 3;
        cp_async16(swz(dst + kc * 8192, r, x),
                   Vth + (size_t)(hk * DHD + r) * S_LEN + kg0 + kc * 32 + x * 8);
    }
}

__global__ __launch_bounds__(128, 2) void flash_hmma(
    const __half* __restrict__ Qh, const __half* __restrict__ Kh,
    const __half* __restrict__ Vth,
    __half* __restrict__ O)
{
    extern __shared__ char smf[];
    const uint32_t sb = smem_u32(smf);
    const int tid = threadIdx.x, wid = tid >> 5, lane = tid & 31;
    const int qt = (int)gridDim.x - 1 - (int)blockIdx.x;   // heavy tiles first
    const int h = blockIdx.y, hk = h >> 2;
    const int qm0 = qt * FBM;
    const int wBase = wid * 16;
    const int lr = lane & 15, lc = lane >> 4;
    const int erow = lane >> 2, q4 = lane & 3;

#pragma unroll
    for (int s = 0; s < 8; s++) {
        int i = tid + 128 * s;
        int c = i >> 8, r = (i >> 2) & 63, x = i & 3;
        cp_async16(swz(sb + FQ_OFF + c * 4096, r, x),
                   Qh + ((size_t)(qm0 + r) * HQ + h) * DHD + c * 32 + x * 8);
    }
    flash_load_k(sb + FK_OFF(0), tid, 0, hk, Kh);
    cp_commit();
    flash_load_v(sb + FV_OFF(0), tid, 0, hk, Vth);
    cp_commit();

    uint32_t qf[8][4];
    float oacc[16][4];
#pragma unroll
    for (int jj = 0; jj < 16; jj++)
#pragma unroll
        for (int x = 0; x < 4; x++) oacc[jj][x] = 0.f;
    float m0 = -1e30f, m1 = -1e30f, l0 = 0.f, l1 = 0.f;

    for (int t = 0; t <= qt; t++) {
        const uint32_t kb = sb + FK_OFF(t & 1);
        const uint32_t vb = sb + FV_OFF(t & 1);

        cp_wait<1>();
        __syncthreads();

        if (t == 0) {
#pragma unroll
            for (int kk = 0; kk < 8; kk++) {
                int c = kk >> 1, x = (kk & 1) * 2 + lc;
                ldsm_x4(qf[kk], swz(sb + FQ_OFF + c * 4096, wBase + lr, x));
            }
        }

        if (t < qt) {
            flash_load_k(sb + FK_OFF((t + 1) & 1), tid, (t + 1) * FBN, hk, Kh);
            cp_commit();
        }

        float sacc[8][4];
#pragma unroll
        for (int j = 0; j < 8; j++)
#pragma unroll
            for (int x = 0; x < 4; x++) sacc[j][x] = 0.f;

#pragma unroll
        for (int kk = 0; kk < 8; kk++) {
            int c = kk >> 1, x = (kk & 1) * 2 + lc;
            uint32_t kbf[4][4];
#pragma unroll
            for (int g = 0; g < 4; g++)
                ldsm_x4(kbf[g], swz(kb + c * 4096, g * 16 + lr, x));
#pragma unroll
            for (int j = 0; j < 8; j++) {
                uint32_t bf[2] = {kbf[j >> 1][j & 1], kbf[j >> 1][(j & 1) + 2]};
                mma_f16(sacc[j], qf[kk], bf, sacc[j]);
            }
        }

        if (t == qt) {
            int row0 = qm0 + wBase + erow, row1 = row0 + 8;
            int colb = t * FBN + q4 * 2;
#pragma unroll
            for (int j = 0; j < 8; j++) {
                int c0 = colb + j * 8, c1 = c0 + 1;
                if (c0 > row0) sacc[j][0] = -1e30f;
                if (c1 > row0) sacc[j][1] = -1e30f;
                if (c0 > row1) sacc[j][2] = -1e30f;
                if (c1 > row1) sacc[j][3] = -1e30f;
            }
        }

        // online softmax in log2 domain
        float mx0 = -1e30f, mx1 = -1e30f;
#pragma unroll
        for (int j = 0; j < 8; j++) {
            mx0 = fmaxf(mx0, fmaxf(sacc[j][0], sacc[j][1]));
            mx1 = fmaxf(mx1, fmaxf(sacc[j][2], sacc[j][3]));
        }
        mx0 = fmaxf(mx0, __shfl_xor_sync(0xFFFFFFFFu, mx0, 1));
        mx0 = fmaxf(mx0, __shfl_xor_sync(0xFFFFFFFFu, mx0, 2));
        mx1 = fmaxf(mx1, __shfl_xor_sync(0xFFFFFFFFu, mx1, 1));
        mx1 = fmaxf(mx1, __shfl_xor_sync(0xFFFFFFFFu, mx1, 2));
        float mn0 = fmaxf(m0, mx0), mn1 = fmaxf(m1, mx1);
        float a0 = exp2f(m0 - mn0), a1 = exp2f(m1 - mn1);
        float s0 = 0.f, s1 = 0.f;
#pragma unroll
        for (int j = 0; j < 8; j++) {
            float p0 = exp2f(sacc[j][0] - mn0); sacc[j][0] = p0; s0 += p0;
            float p1 = exp2f(sacc[j][1] - mn0); sacc[j][1] = p1; s0 += p1;
            float p2 = exp2f(sacc[j][2] - mn1); sacc[j][2] = p2; s1 += p2;
            float p3 = exp2f(sacc[j][3] - mn1); sacc[j][3] = p3; s1 += p3;
        }
        s0 += __shfl_xor_sync(0xFFFFFFFFu, s0, 1);
        s0 += __shfl_xor_sync(0xFFFFFFFFu, s0, 2);
        s1 += __shfl_xor_sync(0xFFFFFFFFu, s1, 1);
        s1 += __shfl_xor_sync(0xFFFFFFFFu, s1, 2);
        l0 = l0 * a0 + s0;
        l1 = l1 * a1 + s1;
        m0 = mn0; m1 = mn1;
#pragma unroll
        for (int jj = 0; jj < 16; jj++) {
            oacc[jj][0] *= a0; oacc[jj][1] *= a0;
            oacc[jj][2] *= a1; oacc[jj][3] *= a1;
        }

        if (t < qt) cp_wait<1>(); else cp_wait<0>();
        __syncthreads();

        if (t < qt) {
            flash_load_v(sb + FV_OFF((t + 1) & 1), tid, (t + 1) * FBN, hk, Vth);
            cp_commit();
        }

        // O += P @ V  (single fp16 P)
#pragma unroll
        for (int tt = 0; tt < 4; tt++) {
            uint32_t ph[4];
            {
                __half2 v0 = __floats2half2_rn(sacc[2*tt][0],   sacc[2*tt][1]);
                __half2 v1 = __floats2half2_rn(sacc[2*tt][2],   sacc[2*tt][3]);
                __half2 v2 = __floats2half2_rn(sacc[2*tt+1][0], sacc[2*tt+1][1]);
                __half2 v3 = __floats2half2_rn(sacc[2*tt+1][2], sacc[2*tt+1][3]);
                ph[0] = *(uint32_t*)&v0; ph[1] = *(uint32_t*)&v1;
                ph[2] = *(uint32_t*)&v2; ph[3] = *(uint32_t*)&v3;
            }
            int kc = tt >> 1, x = (tt & 1) * 2 + lc;
            uint32_t vbf[8][4];
#pragma unroll
            for (int g = 0; g < 8; g++)
                ldsm_x4(vbf[g], swz(vb + kc * 8192, g * 16 + lr, x));
#pragma unroll
            for (int jj = 0; jj < 16; jj++) {
                uint32_t bf[2] = {vbf[jj >> 1][jj & 1], vbf[jj >> 1][(jj & 1) + 2]};
                mma_f16(oacc[jj], ph, bf, oacc[jj]);
            }
        }
    }

    // epilogue: divide by l, write single fp16
    float il0 = 1.0f / l0, il1 = 1.0f / l1;
    int row0 = qm0 + wBase + erow;
#pragma unroll
    for (int jj = 0; jj < 16; jj++) {
        int col = jj * 8 + q4 * 2;
        *(__half2*)(O + (size_t)row0 * QSTR + h * DHD + col) =
            __floats2half2_rn(oacc[jj][0] * il0, oacc[jj][1] * il0);
        *(__half2*)(O + (size_t)(row0 + 8) * QSTR + h * DHD + col) =
            __floats2half2_rn(oacc[jj][2] * il1, oacc[jj][3] * il1);
    }
}

// ------------------------- launch -----------------------------------------------
extern "C" void kernel_launch(void* const* d_in, const int* in_sizes, int n_in,
                              void* d_out, int out_size)
{
    (void)in_sizes; (void)n_in; (void)out_size;
    const float* hs   = (const float*)d_in[0];
    const float* cosp = (const float*)d_in[1];
    const float* sinp = (const float*)d_in[2];
    const float* wq   = (const float*)d_in[3];
    const float* wk   = (const float*)d_in[4];
    const float* wv   = (const float*)d_in[5];
    const float* wo   = (const float*)d_in[6];
    const float* qnw  = (const float*)d_in[7];
    const float* knw  = (const float*)d_in[8];
    float* out = (float*)d_out;

    float *qp, *kp, *vp;
    cudaGetSymbolAddress((void**)&qp, g_q);
    cudaGetSymbolAddress((void**)&kp, g_k);
    cudaGetSymbolAddress((void**)&vp, g_v);
    __half *hsh, *ath, *qh, *kh, *vth;
    __half *wqt, *wkt, *wvt, *wot;
    cudaGetSymbolAddress((void**)&hsh, g_hs);
    cudaGetSymbolAddress((void**)&ath, g_at);
    cudaGetSymbolAddress((void**)&qh, g_qh);
    cudaGetSymbolAddress((void**)&kh, g_kh);
    cudaGetSymbolAddress((void**)&vth, g_vth);
    cudaGetSymbolAddress((void**)&wqt, g_wq);
    cudaGetSymbolAddress((void**)&wkt, g_wk);
    cudaGetSymbolAddress((void**)&wvt, g_wv);
    cudaGetSymbolAddress((void**)&wot, g_wo);

    cudaFuncSetAttribute(gemm_qkv, cudaFuncAttributeMaxDynamicSharedMemorySize, G_SMEM);
    cudaFuncSetAttribute(gemm_f16, cudaFuncAttributeMaxDynamicSharedMemorySize, G_SMEM);
    cudaFuncSetAttribute(flash_hmma, cudaFuncAttributeMaxDynamicSharedMemorySize, F_SMEM);

    // 1) input prep: hs -> fp16, weight transposes (one launch)
    prep_inputs<<<18432, 256>>>(hs, wq, wk, wv, wo, hsh,
                                wqt, wkt, wvt, wot);
    // 2) fused QKV projection (fp16, 128x64 tiles, 2 CTAs/SM)
    gemm_qkv<<<dim3(48, S_LEN / 128), 256, G_SMEM>>>(
        hsh, wqt, wkt, wvt, qp, kp, vp);
    // 3) attention prep: rms+rope Q/K -> fp16 (Q pre-scaled by log2e), V -> vT
    prep_attn<<<12288, 256>>>(qp, kp, vp, cosp, sinp, qnw, knw, qh, kh, vth);
    // 4) causal flash attention (fp16, exp2 softmax)
    flash_hmma<<<dim3(S_LEN / FBM, HQ), 128, F_SMEM>>>(qh, kh, vth, ath);
    // 5) output projection (fp16, 128x64 tiles, 2 CTAs/SM)
    gemm_f16<<<dim3(HIDDEN / 64, S_LEN / 128), 256, G_SMEM>>>(
        ath, wot, out, S_LEN, HIDDEN, QSTR);
}

// round 16
// speedup vs baseline: 1.0927x; 1.0035x over previous
#include <cuda_runtime.h>
#include <cuda_fp16.h>
#include <math.h>
#include <stdint.h>

#define S_LEN 4096
#define HIDDEN 2048
#define HQ 16
#define HKV 4
#define DHD 128
#define QSTR (HQ*DHD)    // 2048
#define KSTR (HKV*DHD)   // 512
#define RMS_EPS 1e-6f
#define SM_SCALE 0.08838834764831845f       // 128^-0.5
#define LOG2E 1.4426950408889634f
#define SM_SCALE_L2 (SM_SCALE * LOG2E)      // folded: scores in log2 domain

// ------------------------- scratch (static device globals) ----------------------
__device__ float g_q[S_LEN * QSTR];
__device__ float g_k[S_LEN * KSTR];
__device__ float g_v[S_LEN * KSTR];

__device__ __half g_hs[S_LEN * HIDDEN];
__device__ __half g_at[S_LEN * QSTR];
__device__ __half g_qh[S_LEN * QSTR];
__device__ __half g_kh[S_LEN * KSTR];
__device__ __half g_vth[KSTR * S_LEN];   // [hk*128+d][s]
__device__ __half g_wq[QSTR * HIDDEN];
__device__ __half g_wk[KSTR * HIDDEN];
__device__ __half g_wv[KSTR * HIDDEN];
__device__ __half g_wo[HIDDEN * QSTR];

// ------------------------- helpers ----------------------------------------------
__device__ __forceinline__ uint32_t smem_u32(const void* p) {
    uint32_t a;
    asm("{ .reg .u64 t; cvta.to.shared.u64 t, %1; cvt.u32.u64 %0, t; }" : "=r"(a) : "l"(p));
    return a;
}
__device__ __forceinline__ void ldsm_x4(uint32_t* r, uint32_t addr) {
    asm volatile("ldmatrix.sync.aligned.m8n8.x4.shared.b16 {%0,%1,%2,%3}, [%4];"
                 : "=r"(r[0]), "=r"(r[1]), "=r"(r[2]), "=r"(r[3]) : "r"(addr));
}
__device__ __forceinline__ void mma_f16(float* d, const uint32_t* a, const uint32_t* b,
                                        const float* c) {
    asm volatile(
        "mma.sync.aligned.m16n8k16.row.col.f32.f16.f16.f32 "
        "{%0,%1,%2,%3}, {%4,%5,%6,%7}, {%8,%9}, {%10,%11,%12,%13};"
        : "=f"(d[0]), "=f"(d[1]), "=f"(d[2]), "=f"(d[3])
        : "r"(a[0]), "r"(a[1]), "r"(a[2]), "r"(a[3]),
          "r"(b[0]), "r"(b[1]),
          "f"(c[0]), "f"(c[1]), "f"(c[2]), "f"(c[3]));
}
__device__ __forceinline__ void cp_async16(uint32_t dst, const void* src) {
    asm volatile("cp.async.cg.shared.global [%0], [%1], 16;" :: "r"(dst), "l"(src) : "memory");
}
__device__ __forceinline__ void cp_commit() {
    asm volatile("cp.async.commit_group;" ::: "memory");
}
template<int N> __device__ __forceinline__ void cp_wait() {
    asm volatile("cp.async.wait_group %0;" :: "n"(N) : "memory");
}
// logical tile rows of 64B (32 fp16) with XOR swizzle
__device__ __forceinline__ uint32_t swz(uint32_t tileBase, int r, int c) {
    uint32_t off = r * 64 + c * 16;
    off ^= ((off >> 7) & 7) << 4;
    return tileBase + off;
}

// ------------------------- transpose device core (fp16 single) -------------------
__device__ __forceinline__ void wt_tile_h(
    const float* __restrict__ W, __half* __restrict__ Th,
    int K, int N, int n0, int k0)
{
    __shared__ float t[32][33];
    int tx = threadIdx.x & 31, ty = threadIdx.x >> 5;
#pragma unroll
    for (int j = 0; j < 4; j++)
        t[ty + 8 * j][tx] = W[(size_t)(k0 + ty + 8 * j) * N + n0 + tx];
    __syncthreads();
#pragma unroll
    for (int j = 0; j < 4; j++) {
        size_t o = (size_t)(n0 + ty + 8 * j) * K + k0 + tx;
        Th[o] = __float2half(t[tx][ty + 8 * j]);
    }
}

// merged input prep: hs fp16 convert (8192 blocks) + 4 weight transposes (10240)
__global__ __launch_bounds__(256) void prep_inputs(
    const float* __restrict__ hs,
    const float* __restrict__ wq, const float* __restrict__ wk,
    const float* __restrict__ wv, const float* __restrict__ wo,
    __half* __restrict__ hsh,
    __half* __restrict__ wqt, __half* __restrict__ wkt,
    __half* __restrict__ wvt, __half* __restrict__ wot)
{
    int b = blockIdx.x;
    if (b < 8192) {
        int i = (b * 256 + threadIdx.x) * 4;
        float4 v = *(const float4*)(hs + i);
        *(__half2*)(hsh + i)     = __floats2half2_rn(v.x, v.y);
        *(__half2*)(hsh + i + 2) = __floats2half2_rn(v.z, v.w);
        return;
    }
    b -= 8192;
    if (b < 4096)
        wt_tile_h(wq, wqt, HIDDEN, QSTR, (b & 63) * 32, (b >> 6) * 32);
    else if (b < 5120) {
        int l = b - 4096;
        wt_tile_h(wk, wkt, HIDDEN, KSTR, (l & 15) * 32, (l >> 4) * 32);
    } else if (b < 6144) {
        int l = b - 5120;
        wt_tile_h(wv, wvt, HIDDEN, KSTR, (l & 15) * 32, (l >> 4) * 32);
    } else {
        int l = b - 6144;
        wt_tile_h(wo, wot, QSTR, HIDDEN, (l & 63) * 32, (l >> 6) * 32);
    }
}

// ------------------------- single-fp16 HMMA GEMM core (K-chunk 64) ---------------
// C = A[M,K] @ B[N,K]^T. CTA 128x64, warp tile 32x32, 8 warps, 2 CTAs/SM.
#define GA_SUB 8192                    // 128x32 fp16 subtile
#define GB_SUB 4096                    // 64x32 fp16 subtile
#define GSTAGE (2 * GA_SUB + 2 * GB_SUB)   // 24576
#define G_SMEM (2 * GSTAGE)                // 49152

__device__ __forceinline__ void gemm_stage(
    uint32_t st, int k0, int tid, int K,
    const __half* __restrict__ A0, const __half* __restrict__ B0)
{
#pragma unroll
    for (int s2 = 0; s2 < 6; s2++) {
        int i = tid + 256 * s2;
        if (i < 1024) {
            int idx = i >> 9;
            int r = (i >> 2) & 127, x = i & 3;
            cp_async16(swz(st + idx * GA_SUB, r, x),
                       A0 + (size_t)r * K + k0 + idx * 32 + x * 8);
        } else {
            int j = i - 1024;
            int idx = j >> 8;
            int r = (j >> 2) & 63, x = j & 3;
            cp_async16(swz(st + 2 * GA_SUB + idx * GB_SUB, r, x),
                       B0 + (size_t)r * K + k0 + idx * 32 + x * 8);
        }
    }
    cp_commit();
}

__device__ __forceinline__ void gemm_core(
    const __half* __restrict__ A0, const __half* __restrict__ B0,
    float* __restrict__ C0, int ldc, int K, uint32_t sb)
{
    const int tid  = threadIdx.x;
    const int wid  = tid >> 5;
    const int lane = tid & 31;
    const int mBase = (wid >> 1) * 32;
    const int nBase = (wid & 1) * 32;
    const int lr = lane & 15, lc = lane >> 4;

    float acc[2][4][4];
#pragma unroll
    for (int f = 0; f < 2; f++)
#pragma unroll
        for (int j = 0; j < 4; j++)
#pragma unroll
            for (int x = 0; x < 4; x++) acc[f][j][x] = 0.f;

    const int nChunks = K >> 6;
    gemm_stage(sb, 0, tid, K, A0, B0);

    for (int kc = 0; kc < nChunks; kc++) {
        const uint32_t st = sb + (kc & 1) * GSTAGE;
        if (kc + 1 < nChunks) {
            gemm_stage(sb + ((kc + 1) & 1) * GSTAGE, (kc + 1) << 6, tid, K, A0, B0);
            cp_wait<1>();
        } else {
            cp_wait<0>();
        }
        __syncthreads();

#pragma unroll
        for (int s16 = 0; s16 < 4; s16++) {
            const int sub = s16 >> 1;
            const int ch  = (s16 & 1) * 2 + lc;
            const uint32_t tA = st + sub * GA_SUB;
            const uint32_t tB = st + 2 * GA_SUB + sub * GB_SUB;

            uint32_t ah[2][4], bb[2][4];
#pragma unroll
            for (int f = 0; f < 2; f++)
                ldsm_x4(ah[f], swz(tA, mBase + f * 16 + lr, ch));
#pragma unroll
            for (int g = 0; g < 2; g++)
                ldsm_x4(bb[g], swz(tB, nBase + g * 16 + lr, ch));
#pragma unroll
            for (int f = 0; f < 2; f++)
#pragma unroll
                for (int j = 0; j < 4; j++) {
                    uint32_t bfr[2] = {bb[j >> 1][j & 1], bb[j >> 1][2 + (j & 1)]};
                    mma_f16(acc[f][j], ah[f], bfr, acc[f][j]);
                }
        }
        __syncthreads();
    }

    const int erow = lane >> 2;
    const int ecol = (lane & 3) * 2;
#pragma unroll
    for (int f = 0; f < 2; f++) {
        int rl = mBase + f * 16 + erow;
#pragma unroll
        for (int j = 0; j < 4; j++) {
            int cl = nBase + j * 8 + ecol;
            *(float2*)(C0 + (size_t)rl * ldc + cl)       = make_float2(acc[f][j][0], acc[f][j][1]);
            *(float2*)(C0 + (size_t)(rl + 8) * ldc + cl) = make_float2(acc[f][j][2], acc[f][j][3]);
        }
    }
}

__global__ __launch_bounds__(256, 2) void gemm_qkv(
    const __half* __restrict__ A,
    const __half* __restrict__ wqt, const __half* __restrict__ wkt,
    const __half* __restrict__ wvt,
    float* __restrict__ Q, float* __restrict__ K, float* __restrict__ V)
{
    extern __shared__ char smc[];
    const uint32_t sb = smem_u32(smc);
    const int bx = blockIdx.x;
    const int m0 = blockIdx.y * 128;

    const __half* B;
    float* C;
    int n0, ldc;
    if (bx < 32)      { B = wqt; C = Q; n0 = bx * 64;        ldc = QSTR; }
    else if (bx < 40) { B = wkt; C = K; n0 = (bx - 32) * 64; ldc = KSTR; }
    else              { B = wvt; C = V; n0 = (bx - 40) * 64; ldc = KSTR; }

    gemm_core(A + (size_t)m0 * HIDDEN, B + (size_t)n0 * HIDDEN,
              C + (size_t)m0 * ldc + n0, ldc, HIDDEN, sb);
}

__global__ __launch_bounds__(256, 2) void gemm_f16(
    const __half* __restrict__ A, const __half* __restrict__ B,
    float* __restrict__ C, int M, int N, int K)
{
    extern __shared__ char smc[];
    const uint32_t sb = smem_u32(smc);
    const int m0 = blockIdx.y * 128, n0 = blockIdx.x * 64;
    gemm_core(A + (size_t)m0 * K, B + (size_t)n0 * K,
              C + (size_t)m0 * N + n0, N, K, sb);
}

// ------------------------- fused attention prep (one launch) ---------------------
__device__ __forceinline__ void rms_rope_rows_h(
    const float* __restrict__ in, const float* __restrict__ cosp,
    const float* __restrict__ sinp, const float* __restrict__ w,
    int nh, float outScale, int rowBase, __half* __restrict__ H)
{
    const int lane = threadIdx.x & 31;
    const int rowIdx = rowBase + (threadIdx.x >> 5);
    const int s = rowIdx / nh;
    const int d0 = lane * 2;

    const float* x = in + (size_t)rowIdx * DHD;
    float2 a = *(const float2*)(x + d0);
    float2 b = *(const float2*)(x + 64 + d0);

    float ss = a.x * a.x + a.y * a.y + b.x * b.x + b.y * b.y;
#pragma unroll
    for (int o = 16; o > 0; o >>= 1) ss += __shfl_xor_sync(0xFFFFFFFFu, ss, o);
    float inv = rsqrtf(ss * (1.0f / DHD) + RMS_EPS);

    float2 wa = *(const float2*)(w + d0);
    float2 wb = *(const float2*)(w + 64 + d0);
    const float* cs = cosp + (size_t)s * DHD;
    const float* sn = sinp + (size_t)s * DHD;
    float2 ca = *(const float2*)(cs + d0), cb = *(const float2*)(cs + 64 + d0);
    float2 sa = *(const float2*)(sn + d0), sb2 = *(const float2*)(sn + 64 + d0);

    float xa0 = a.x * inv * wa.x, xa1 = a.y * inv * wa.y;
    float xb0 = b.x * inv * wb.x, xb1 = b.y * inv * wb.y;
    float oa0 = (xa0 * ca.x - xb0 * sa.x) * outScale;
    float oa1 = (xa1 * ca.y - xb1 * sa.y) * outScale;
    float ob0 = (xb0 * cb.x + xa0 * sb2.x) * outScale;
    float ob1 = (xb1 * cb.y + xa1 * sb2.y) * outScale;

    size_t off = (size_t)rowIdx * DHD + d0;
    *(__half2*)(H + off)      = __floats2half2_rn(oa0, oa1);
    *(__half2*)(H + off + 64) = __floats2half2_rn(ob0, ob1);
}

__global__ __launch_bounds__(256) void prep_attn(
    const float* __restrict__ qp, const float* __restrict__ kp,
    const float* __restrict__ vp,
    const float* __restrict__ cosp, const float* __restrict__ sinp,
    const float* __restrict__ qnw, const float* __restrict__ knw,
    __half* __restrict__ qh, __half* __restrict__ kh,
    __half* __restrict__ vth)
{
    int b = blockIdx.x;
    if (b < 8192)
        rms_rope_rows_h(qp, cosp, sinp, qnw, HQ, SM_SCALE_L2, b * 8, qh);
    else if (b < 10240)
        rms_rope_rows_h(kp, cosp, sinp, knw, HKV, 1.0f, (b - 8192) * 8, kh);
    else {
        int l = b - 10240;
        wt_tile_h(vp, vth, S_LEN, KSTR, (l & 15) * 32, (l >> 4) * 32);
    }
}

// ------------------------- fp16 HMMA causal flash attention ----------------------
// exp2 softmax (log2e folded into Q). S-phase K fragments register-double-buffered
// so ldsm for step kk+1 issues before the mma block of step kk.
#define FBM 64
#define FBN 64
#define FQ_OFF 0
#define FK_OFF(i) (16384 + (i) * 16384)
#define FV_OFF(i) (49152 + (i) * 16384)
#define F_SMEM 81920

__device__ __forceinline__ void flash_load_k(
    uint32_t dst, int tid, int kg0, int hk, const __half* Kh)
{
#pragma unroll
    for (int s = 0; s < 8; s++) {
        int i = tid + 128 * s;
        int c = i >> 8, r = (i >> 2) & 63, x = i & 3;
        cp_async16(swz(dst + c * 4096, r, x),
                   Kh + ((size_t)(kg0 + r) * HKV + hk) * DHD + c * 32 + x * 8);
    }
}
__device__ __forceinline__ void flash_load_v(
    uint32_t dst, int tid, int kg0, int hk, const __half* Vth)
{
#pragma unroll
    for (int s = 0; s < 8; s++) {
        int i = tid + 128 * s;
        int kc = i >> 9, r = (i >> 2) & 127, x = i & 3;
        cp_async16(swz(dst + kc * 8192, r, x),
                   Vth + (size_t)(hk * DHD + r) * S_LEN + kg0 + kc * 32 + x * 8);
    }
}

__global__ __launch_bounds__(128, 2) void flash_hmma(
    const __half* __restrict__ Qh, const __half* __restrict__ Kh,
    const __half* __restrict__ Vth,
    __half* __restrict__ O)
{
    extern __shared__ char smf[];
    const uint32_t sb = smem_u32(smf);
    const int tid = threadIdx.x, wid = tid >> 5, lane = tid & 31;
    const int qt = (int)gridDim.x - 1 - (int)blockIdx.x;   // heavy tiles first
    const int h = blockIdx.y, hk = h >> 2;
    const int qm0 = qt * FBM;
    const int wBase = wid * 16;
    const int lr = lane & 15, lc = lane >> 4;
    const int erow = lane >> 2, q4 = lane & 3;

#pragma unroll
    for (int s = 0; s < 8; s++) {
        int i = tid + 128 * s;
        int c = i >> 8, r = (i >> 2) & 63, x = i & 3;
        cp_async16(swz(sb + FQ_OFF + c * 4096, r, x),
                   Qh + ((size_t)(qm0 + r) * HQ + h) * DHD + c * 32 + x * 8);
    }
    flash_load_k(sb + FK_OFF(0), tid, 0, hk, Kh);
    cp_commit();
    flash_load_v(sb + FV_OFF(0), tid, 0, hk, Vth);
    cp_commit();

    uint32_t qf[8][4];
    float oacc[16][4];
#pragma unroll
    for (int jj = 0; jj < 16; jj++)
#pragma unroll
        for (int x = 0; x < 4; x++) oacc[jj][x] = 0.f;
    float m0 = -1e30f, m1 = -1e30f, l0 = 0.f, l1 = 0.f;

    for (int t = 0; t <= qt; t++) {
        const uint32_t kb = sb + FK_OFF(t & 1);
        const uint32_t vb = sb + FV_OFF(t & 1);

        cp_wait<1>();
        __syncthreads();

        if (t == 0) {
#pragma unroll
            for (int kk = 0; kk < 8; kk++) {
                int c = kk >> 1, x = (kk & 1) * 2 + lc;
                ldsm_x4(qf[kk], swz(sb + FQ_OFF + c * 4096, wBase + lr, x));
            }
        }

        if (t < qt) {
            flash_load_k(sb + FK_OFF((t + 1) & 1), tid, (t + 1) * FBN, hk, Kh);
            cp_commit();
        }

        // ---- S = Q @ K^T, K frags double-buffered in registers
        float sacc[8][4];
#pragma unroll
        for (int j = 0; j < 8; j++)
#pragma unroll
            for (int x = 0; x < 4; x++) sacc[j][x] = 0.f;

        uint32_t kbf[2][4][4];
#pragma unroll
        for (int g = 0; g < 4; g++)
            ldsm_x4(kbf[0][g], swz(kb, g * 16 + lr, lc));
#pragma unroll
        for (int kk = 0; kk < 8; kk++) {
            const int cur = kk & 1;
            if (kk < 7) {
                int c = (kk + 1) >> 1, x = ((kk + 1) & 1) * 2 + lc;
#pragma unroll
                for (int g = 0; g < 4; g++)
                    ldsm_x4(kbf[cur ^ 1][g], swz(kb + c * 4096, g * 16 + lr, x));
            }
#pragma unroll
            for (int j = 0; j < 8; j++) {
                uint32_t bf[2] = {kbf[cur][j >> 1][j & 1], kbf[cur][j >> 1][(j & 1) + 2]};
                mma_f16(sacc[j], qf[kk], bf, sacc[j]);
            }
        }

        if (t == qt) {
            int row0 = qm0 + wBase + erow, row1 = row0 + 8;
            int colb = t * FBN + q4 * 2;
#pragma unroll
            for (int j = 0; j < 8; j++) {
                int c0 = colb + j * 8, c1 = c0 + 1;
                if (c0 > row0) sacc[j][0] = -1e30f;
                if (c1 > row0) sacc[j][1] = -1e30f;
                if (c0 > row1) sacc[j][2] = -1e30f;
                if (c1 > row1) sacc[j][3] = -1e30f;
            }
        }

        // online softmax in log2 domain
        float mx0 = -1e30f, mx1 = -1e30f;
#pragma unroll
        for (int j = 0; j < 8; j++) {
            mx0 = fmaxf(mx0, fmaxf(sacc[j][0], sacc[j][1]));
            mx1 = fmaxf(mx1, fmaxf(sacc[j][2], sacc[j][3]));
        }
        mx0 = fmaxf(mx0, __shfl_xor_sync(0xFFFFFFFFu, mx0, 1));
        mx0 = fmaxf(mx0, __shfl_xor_sync(0xFFFFFFFFu, mx0, 2));
        mx1 = fmaxf(mx1, __shfl_xor_sync(0xFFFFFFFFu, mx1, 1));
        mx1 = fmaxf(mx1, __shfl_xor_sync(0xFFFFFFFFu, mx1, 2));
        float mn0 = fmaxf(m0, mx0), mn1 = fmaxf(m1, mx1);
        float a0 = exp2f(m0 - mn0), a1 = exp2f(m1 - mn1);
        float s0 = 0.f, s1 = 0.f;
#pragma unroll
        for (int j = 0; j < 8; j++) {
            float p0 = exp2f(sacc[j][0] - mn0); sacc[j][0] = p0; s0 += p0;
            float p1 = exp2f(sacc[j][1] - mn0); sacc[j][1] = p1; s0 += p1;
            float p2 = exp2f(sacc[j][2] - mn1); sacc[j][2] = p2; s1 += p2;
            float p3 = exp2f(sacc[j][3] - mn1); sacc[j][3] = p3; s1 += p3;
        }
        s0 += __shfl_xor_sync(0xFFFFFFFFu, s0, 1);
        s0 += __shfl_xor_sync(0xFFFFFFFFu, s0, 2);
        s1 += __shfl_xor_sync(0xFFFFFFFFu, s1, 1);
        s1 += __shfl_xor_sync(0xFFFFFFFFu, s1, 2);
        l0 = l0 * a0 + s0;
        l1 = l1 * a1 + s1;
        m0 = mn0; m1 = mn1;
#pragma unroll
        for (int jj = 0; jj < 16; jj++) {
            oacc[jj][0] *= a0; oacc[jj][1] *= a0;
            oacc[jj][2] *= a1; oacc[jj][3] *= a1;
        }

        if (t < qt) cp_wait<1>(); else cp_wait<0>();
        __syncthreads();

        if (t < qt) {
            flash_load_v(sb + FV_OFF((t + 1) & 1), tid, (t + 1) * FBN, hk, Vth);
            cp_commit();
        }

        // O += P @ V  (single fp16 P)
#pragma unroll
        for (int tt = 0; tt < 4; tt++) {
            uint32_t ph[4];
            {
                __half2 v0 = __floats2half2_rn(sacc[2*tt][0],   sacc[2*tt][1]);
                __half2 v1 = __floats2half2_rn(sacc[2*tt][2],   sacc[2*tt][3]);
                __half2 v2 = __floats2half2_rn(sacc[2*tt+1][0], sacc[2*tt+1][1]);
                __half2 v3 = __floats2half2_rn(sacc[2*tt+1][2], sacc[2*tt+1][3]);
                ph[0] = *(uint32_t*)&v0; ph[1] = *(uint32_t*)&v1;
                ph[2] = *(uint32_t*)&v2; ph[3] = *(uint32_t*)&v3;
            }
            int kc = tt >> 1, x = (tt & 1) * 2 + lc;
            uint32_t vbf[8][4];
#pragma unroll
            for (int g = 0; g < 8; g++)
                ldsm_x4(vbf[g], swz(vb + kc * 8192, g * 16 + lr, x));
#pragma unroll
            for (int jj = 0; jj < 16; jj++) {
                uint32_t bf[2] = {vbf[jj >> 1][jj & 1], vbf[jj >> 1][(jj & 1) + 2]};
                mma_f16(oacc[jj], ph, bf, oacc[jj]);
            }
        }
    }

    // epilogue: divide by l, write single fp16
    float il0 = 1.0f / l0, il1 = 1.0f / l1;
    int row0 = qm0 + wBase + erow;
#pragma unroll
    for (int jj = 0; jj < 16; jj++) {
        int col = jj * 8 + q4 * 2;
        *(__half2*)(O + (size_t)row0 * QSTR + h * DHD + col) =
            __floats2half2_rn(oacc[jj][0] * il0, oacc[jj][1] * il0);
        *(__half2*)(O + (size_t)(row0 + 8) * QSTR + h * DHD + col) =
            __floats2half2_rn(oacc[jj][2] * il1, oacc[jj][3] * il1);
    }
}

// ------------------------- launch -----------------------------------------------
extern "C" void kernel_launch(void* const* d_in, const int* in_sizes, int n_in,
                              void* d_out, int out_size)
{
    (void)in_sizes; (void)n_in; (void)out_size;
    const float* hs   = (const float*)d_in[0];
    const float* cosp = (const float*)d_in[1];
    const float* sinp = (const float*)d_in[2];
    const float* wq   = (const float*)d_in[3];
    const float* wk   = (const float*)d_in[4];
    const float* wv   = (const float*)d_in[5];
    const float* wo   = (const float*)d_in[6];
    const float* qnw  = (const float*)d_in[7];
    const float* knw  = (const float*)d_in[8];
    float* out = (float*)d_out;

    float *qp, *kp, *vp;
    cudaGetSymbolAddress((void**)&qp, g_q);
    cudaGetSymbolAddress((void**)&kp, g_k);
    cudaGetSymbolAddress((void**)&vp, g_v);
    __half *hsh, *ath, *qh, *kh, *vth;
    __half *wqt, *wkt, *wvt, *wot;
    cudaGetSymbolAddress((void**)&hsh, g_hs);
    cudaGetSymbolAddress((void**)&ath, g_at);
    cudaGetSymbolAddress((void**)&qh, g_qh);
    cudaGetSymbolAddress((void**)&kh, g_kh);
    cudaGetSymbolAddress((void**)&vth, g_vth);
    cudaGetSymbolAddress((void**)&wqt, g_wq);
    cudaGetSymbolAddress((void**)&wkt, g_wk);
    cudaGetSymbolAddress((void**)&wvt, g_wv);
    cudaGetSymbolAddress((void**)&wot, g_wo);

    cudaFuncSetAttribute(gemm_qkv, cudaFuncAttributeMaxDynamicSharedMemorySize, G_SMEM);
    cudaFuncSetAttribute(gemm_f16, cudaFuncAttributeMaxDynamicSharedMemorySize, G_SMEM);
    cudaFuncSetAttribute(flash_hmma, cudaFuncAttributeMaxDynamicSharedMemorySize, F_SMEM);

    // 1) input prep: hs -> fp16, weight transposes (one launch)
    prep_inputs<<<18432, 256>>>(hs, wq, wk, wv, wo, hsh,
                                wqt, wkt, wvt, wot);
    // 2) fused QKV projection (fp16, 128x64 tiles, 2 CTAs/SM)
    gemm_qkv<<<dim3(48, S_LEN / 128), 256, G_SMEM>>>(
        hsh, wqt, wkt, wvt, qp, kp, vp);
    // 3) attention prep: rms+rope Q/K -> fp16 (Q pre-scaled by log2e), V -> vT
    prep_attn<<<12288, 256>>>(qp, kp, vp, cosp, sinp, qnw, knw, qh, kh, vth);
    // 4) causal flash attention (fp16, exp2 softmax, reg-pipelined S phase)
    flash_hmma<<<dim3(S_LEN / FBM, HQ), 128, F_SMEM>>>(qh, kh, vth, ath);
    // 5) output projection (fp16, 128x64 tiles, 2 CTAs/SM)
    gemm_f16<<<dim3(HIDDEN / 64, S_LEN / 128), 256, G_SMEM>>>(
        ath, wot, out, S_LEN, HIDDEN, QSTR);
}